// round 15
// baseline (speedup 1.0000x reference)
#include <cuda_runtime.h>
#include <cstdint>

#define BB   64
#define CHN  3
#define HWP  (224*224)
#define KBIG (CHN*HWP)
#define EMB  512
#define CONC 812
#define HID  400

__device__ float g_concat[BB*CONC];     // [64][812]: xm | hist
__device__ float g_h[BB*HID];           // [64][400] pre-activation
__device__ float g_hid[BB*1400];        // [64][600|400|400] pre-activation
__device__ unsigned g_mm[BB*CHN*2];     // per-(b,c) min/max as monotone keys

__device__ __forceinline__ uint32_t smem_u32(const void* p) {
    uint32_t a;
    asm("{ .reg .u64 t; cvta.to.shared.u64 t, %1; cvt.u32.u64 %0, t; }" : "=r"(a) : "l"(p));
    return a;
}

__device__ __forceinline__ void ldm4(uint32_t* r, uint32_t addr) {
    asm volatile("ldmatrix.sync.aligned.m8n8.x4.shared.b16 {%0,%1,%2,%3}, [%4];"
        : "=r"(r[0]), "=r"(r[1]), "=r"(r[2]), "=r"(r[3]) : "r"(addr));
}

__device__ __forceinline__ void mma16816(float* d, const uint32_t* a, const uint32_t* b) {
    asm volatile("mma.sync.aligned.m16n8k16.row.col.f32.bf16.bf16.f32 "
        "{%0,%1,%2,%3}, {%4,%5,%6,%7}, {%8,%9}, {%0,%1,%2,%3};"
        : "+f"(d[0]), "+f"(d[1]), "+f"(d[2]), "+f"(d[3])
        : "r"(a[0]), "r"(a[1]), "r"(a[2]), "r"(a[3]), "r"(b[0]), "r"(b[1]));
}

// split fp32x4 -> bf16 hi pair + bf16 lo pair (low halfword = lower k)
__device__ __forceinline__ void cvt_split(float4 v, uint32_t& h01, uint32_t& h23,
                                          uint32_t& l01, uint32_t& l23) {
    asm("cvt.rn.bf16x2.f32 %0, %1, %2;" : "=r"(h01) : "f"(v.y), "f"(v.x));
    asm("cvt.rn.bf16x2.f32 %0, %1, %2;" : "=r"(h23) : "f"(v.w), "f"(v.z));
    float r0 = v.x - __uint_as_float(h01 << 16);
    float r1 = v.y - __uint_as_float(h01 & 0xffff0000u);
    float r2 = v.z - __uint_as_float(h23 << 16);
    float r3 = v.w - __uint_as_float(h23 & 0xffff0000u);
    asm("cvt.rn.bf16x2.f32 %0, %1, %2;" : "=r"(l01) : "f"(r1), "f"(r0));
    asm("cvt.rn.bf16x2.f32 %0, %1, %2;" : "=r"(l23) : "f"(r3), "f"(r2));
}

// mbarrier helpers
__device__ __forceinline__ void mbar_init(uint32_t a, uint32_t cnt) {
    asm volatile("mbarrier.init.shared.b64 [%0], %1;" :: "r"(a), "r"(cnt) : "memory");
}
__device__ __forceinline__ void mbar_arrive(uint32_t a) {
    uint64_t st;
    asm volatile("mbarrier.arrive.shared.b64 %0, [%1];" : "=l"(st) : "r"(a) : "memory");
}
__device__ __forceinline__ void mbar_wait(uint32_t a, uint32_t parity) {
    asm volatile(
        "{\n\t.reg .pred P;\n\t"
        "WL_%=:\n\t"
        "mbarrier.try_wait.parity.acquire.cta.shared::cta.b64 P, [%0], %1, 0x989680;\n\t"
        "@P bra.uni WD_%=;\n\t"
        "bra.uni WL_%=;\n\t"
        "WD_%=:\n\t}"
        :: "r"(a), "r"(parity) : "memory");
}

// monotone key transform for float atomic min/max on uint
__device__ __forceinline__ unsigned fkey(float f) {
    unsigned b = __float_as_uint(f);
    return (b & 0x80000000u) ? ~b : (b | 0x80000000u);
}
__device__ __forceinline__ float funkey(unsigned k) {
    unsigned b = (k & 0x80000000u) ? (k & 0x7fffffffu) : ~k;
    return __uint_as_float(b);
}

// ===== big GEMM: concat[b,n] += x[b,:].W[n,:]  (bf16 3-term split, HMMA) =====
// Warp-specialized, 64m x 256n CTA tile, KT=64, 2-stage 80KB ring, 1 CTA/SM.
// Term-major mma ordering (acc RAW distance 16) + early empty-arrive.
#define KSPLIT 74
#define BUFSZ  81920    // x hi 8K | x lo 8K | W hi 32K | W lo 32K
#define G1_SMEM (2 * BUFSZ + 64)

__global__ __launch_bounds__(384, 1) void gemm1(const float* __restrict__ x,
                                                const float* __restrict__ W) {
    extern __shared__ __align__(128) uint8_t smraw[];
    uint32_t base = smem_u32(smraw);
    uint32_t MB = base + 2 * BUFSZ;           // full[0],full[1],empty[0],empty[1]

    int tid = threadIdx.x, wid = tid >> 5, lane = tid & 31;
    int n0 = blockIdx.x * 256;
    int ky = blockIdx.y;
    int t0 = ky * 31 + (ky < 58 ? ky : 58);
    int cnt = 31 + (ky < 58 ? 1 : 0);

    if (tid == 0) {
        mbar_init(MB + 0, 128);   // full[0]
        mbar_init(MB + 8, 128);   // full[1]
        mbar_init(MB + 16, 256);  // empty[0]
        mbar_init(MB + 24, 256);  // empty[1]
    }
    __syncthreads();

    if (wid >= 8) {
        // ---------------- producers (warps 8-11, 128 threads) ----------------
        int p = tid - 256;
        int prow = p >> 4, pc4 = p & 15;
        const float* xbase = x + (size_t)prow * KBIG + pc4 * 4;
        const float* wbase = W + (size_t)(n0 + prow) * KBIG + pc4 * 4;
        uint32_t swz = (uint32_t)((pc4 * 8) ^ ((prow & 7) << 4));
        int phE0 = 0, phE1 = 0;
        for (int it = 0; it < cnt; ++it) {
            int s = it & 1;
            if (it >= 2) {
                if (s == 0) { mbar_wait(MB + 16, phE0); phE0 ^= 1; }
                else        { mbar_wait(MB + 24, phE1); phE1 ^= 1; }
            }
            uint32_t bb_ = base + s * BUFSZ;
            uint32_t XHI = bb_, XLO = bb_ + 8192, WHI = bb_ + 16384, WLO = bb_ + 49152;
            size_t k0 = (size_t)(t0 + it) * 64;
            float4 v[8];
            // x tile 64x64: 8 float4 per thread
            #pragma unroll
            for (int j = 0; j < 8; j++) v[j] = *(const float4*)(xbase + (size_t)(j * 8) * KBIG + k0);
            #pragma unroll
            for (int j = 0; j < 8; j++) {
                uint32_t off = (uint32_t)((prow + j * 8) * 128) + swz;
                uint32_t h01, h23, l01, l23;
                cvt_split(v[j], h01, h23, l01, l23);
                asm volatile("st.shared.v2.b32 [%0], {%1, %2};" :: "r"(XHI + off), "r"(h01), "r"(h23));
                asm volatile("st.shared.v2.b32 [%0], {%1, %2};" :: "r"(XLO + off), "r"(l01), "r"(l23));
            }
            // W tile 256x64: 32 float4 per thread, 4 chunks of 8
            #pragma unroll
            for (int c = 0; c < 4; c++) {
                #pragma unroll
                for (int j = 0; j < 8; j++)
                    v[j] = *(const float4*)(wbase + (size_t)((c * 8 + j) * 8) * KBIG + k0);
                #pragma unroll
                for (int j = 0; j < 8; j++) {
                    uint32_t off = (uint32_t)((prow + (c * 8 + j) * 8) * 128) + swz;
                    uint32_t h01, h23, l01, l23;
                    cvt_split(v[j], h01, h23, l01, l23);
                    asm volatile("st.shared.v2.b32 [%0], {%1, %2};" :: "r"(WHI + off), "r"(h01), "r"(h23));
                    asm volatile("st.shared.v2.b32 [%0], {%1, %2};" :: "r"(WLO + off), "r"(l01), "r"(l23));
                }
            }
            mbar_arrive(MB + s * 8);   // full[s]
        }
        return;
    }

    // ---------------- consumers (warps 0-7): 32m x 64n each ----------------
    int warp_m = wid >> 2;
    int warp_n = wid & 3;
    int ar = lane & 7, ag = lane >> 3;
    int a_row_off = (ag & 1) * 8 + ar;
    int a_col_off = (ag >> 1) * 16;
    int b_row_off = (ag >> 1) * 8 + ar;
    int b_col_off = (ag & 1) * 16;

    float acc[2][8][4];
    #pragma unroll
    for (int i = 0; i < 2; i++)
        #pragma unroll
        for (int j = 0; j < 8; j++)
            #pragma unroll
            for (int q = 0; q < 4; q++) acc[i][j][q] = 0.f;

    int phF0 = 0, phF1 = 0;
    for (int it = 0; it < cnt; ++it) {
        int s = it & 1;
        if (s == 0) { mbar_wait(MB + 0, phF0); phF0 ^= 1; }
        else        { mbar_wait(MB + 8, phF1); phF1 ^= 1; }
        uint32_t bb_ = base + s * BUFSZ;
        uint32_t XHI = bb_, XLO = bb_ + 8192, WHI = bb_ + 16384, WLO = bb_ + 49152;
        #pragma unroll
        for (int ks = 0; ks < 4; ++ks) {
            int cbase = ks * 32;
            uint32_t ah[2][4], al[2][4], bh[4][4], bl[4][4];
            #pragma unroll
            for (int mi = 0; mi < 2; mi++) {
                int r = warp_m * 32 + mi * 16 + a_row_off;
                uint32_t col = (uint32_t)(cbase + a_col_off) ^ ((r & 7) << 4);
                ldm4(ah[mi], XHI + r * 128 + col);
                ldm4(al[mi], XLO + r * 128 + col);
            }
            #pragma unroll
            for (int ni = 0; ni < 4; ni++) {
                int r = warp_n * 64 + ni * 16 + b_row_off;
                uint32_t col = (uint32_t)(cbase + b_col_off) ^ ((r & 7) << 4);
                ldm4(bh[ni], WHI + r * 128 + col);
                ldm4(bl[ni], WLO + r * 128 + col);
            }
            if (ks == 3) mbar_arrive(MB + 16 + s * 8);   // early empty[s]: all smem reads done
            // term-major: 16 independent accs per pass -> no acc RAW stalls
            #pragma unroll
            for (int mi = 0; mi < 2; mi++)
                #pragma unroll
                for (int ni = 0; ni < 4; ni++)
                    #pragma unroll
                    for (int nj = 0; nj < 2; nj++)
                        mma16816(acc[mi][ni * 2 + nj], ah[mi], bh[ni] + nj * 2);
            #pragma unroll
            for (int mi = 0; mi < 2; mi++)
                #pragma unroll
                for (int ni = 0; ni < 4; ni++)
                    #pragma unroll
                    for (int nj = 0; nj < 2; nj++)
                        mma16816(acc[mi][ni * 2 + nj], ah[mi], bl[ni] + nj * 2);
            #pragma unroll
            for (int mi = 0; mi < 2; mi++)
                #pragma unroll
                for (int ni = 0; ni < 4; ni++)
                    #pragma unroll
                    for (int nj = 0; nj < 2; nj++)
                        mma16816(acc[mi][ni * 2 + nj], al[mi], bh[ni] + nj * 2);
        }
    }

    #pragma unroll
    for (int mi = 0; mi < 2; mi++) {
        int b = warp_m * 32 + mi * 16 + (lane >> 2);
        #pragma unroll
        for (int g = 0; g < 8; g++) {
            int n = n0 + warp_n * 64 + (g >> 1) * 16 + (g & 1) * 8 + (lane & 3) * 2;
            atomicAdd(&g_concat[b * CONC + n],           acc[mi][g][0]);
            atomicAdd(&g_concat[b * CONC + n + 1],       acc[mi][g][1]);
            atomicAdd(&g_concat[(b + 8) * CONC + n],     acc[mi][g][2]);
            atomicAdd(&g_concat[(b + 8) * CONC + n + 1], acc[mi][g][3]);
        }
    }
}

// ======================= merged init =======================
#define INIT_TOTAL (32768 + 25600 + 89600 + 19200 + 384)
__global__ void init_all(const float* __restrict__ bb, const float* __restrict__ hb,
                         const float* __restrict__ stb1, const float* __restrict__ ageb1,
                         const float* __restrict__ genb1) {
    int i = blockIdx.x * 256 + threadIdx.x;
    if (i < 32768) { g_concat[(i >> 9) * CONC + (i & 511)] = bb[i & 511]; return; }
    i -= 32768;
    if (i < 25600) { g_h[i] = hb[i % HID]; return; }
    i -= 25600;
    if (i < 89600) {
        int c = i % 1400;
        g_hid[i] = (c < 600) ? stb1[c] : (c < 1000 ? ageb1[c - 600] : genb1[c - 1000]);
        return;
    }
    i -= 89600;
    if (i < 19200) {
        int b = i / 300, c = i % 300;
        g_concat[b * CONC + EMB + c] = 0.f;
        return;
    }
    i -= 19200;
    if (i < 384) g_mm[i] = (i & 1) ? 0u : 0xFFFFFFFFu;
}

// ============ hist pass 1: min/max, 4 CTAs per (b,c) row ============
#define SEG (HWP / 4)
__global__ __launch_bounds__(256) void hist_minmax(const float* __restrict__ x) {
    int r = blockIdx.x >> 2, seg = blockIdx.x & 3;
    const float4* rg = (const float4*)(x + (size_t)r * HWP + (size_t)seg * SEG);
    __shared__ unsigned s_red[16];
    int t = threadIdx.x, w = t >> 5, lane = t & 31;
    float mn = 1e30f, mx = -1e30f;
    for (int i = t; i < SEG / 4; i += 256) {
        float4 v = rg[i];
        mn = fminf(mn, fminf(fminf(v.x, v.y), fminf(v.z, v.w)));
        mx = fmaxf(mx, fmaxf(fmaxf(v.x, v.y), fmaxf(v.z, v.w)));
    }
    for (int o = 16; o > 0; o >>= 1) {
        mn = fminf(mn, __shfl_xor_sync(0xffffffffu, mn, o));
        mx = fmaxf(mx, __shfl_xor_sync(0xffffffffu, mx, o));
    }
    if (lane == 0) { s_red[w] = fkey(mn); s_red[8 + w] = fkey(mx); }
    __syncthreads();
    if (t == 0) {
        unsigned a = s_red[0], b = s_red[8];
        for (int k = 1; k < 8; k++) { a = min(a, s_red[k]); b = max(b, s_red[8 + k]); }
        atomicMin(&g_mm[r * 2], a);
        atomicMax(&g_mm[r * 2 + 1], b);
    }
}

// ============ hist pass 2: binning, 4 CTAs per row ============
__global__ __launch_bounds__(256) void hist_bins(const float* __restrict__ x) {
    int r = blockIdx.x >> 2, seg = blockIdx.x & 3;
    const float4* rg = (const float4*)(x + (size_t)r * HWP + (size_t)seg * SEG);
    __shared__ int s_bins[8][100];
    int t = threadIdx.x, w = t >> 5;
    for (int i = t; i < 800; i += 256) s_bins[0][i] = 0;
    __syncthreads();
    float mnv = funkey(g_mm[r * 2]);
    float mxv = funkey(g_mm[r * 2 + 1]);
    float width = (mxv > mnv) ? (mxv - mnv) : 1.0f;
    for (int i = t; i < SEG / 4; i += 256) {
        float4 v = rg[i];
        int i0 = (int)floorf((v.x - mnv) / width * 100.0f);
        int i1 = (int)floorf((v.y - mnv) / width * 100.0f);
        int i2 = (int)floorf((v.z - mnv) / width * 100.0f);
        int i3 = (int)floorf((v.w - mnv) / width * 100.0f);
        i0 = min(max(i0, 0), 99); i1 = min(max(i1, 0), 99);
        i2 = min(max(i2, 0), 99); i3 = min(max(i3, 0), 99);
        atomicAdd(&s_bins[w][i0], 1);
        atomicAdd(&s_bins[w][i1], 1);
        atomicAdd(&s_bins[w][i2], 1);
        atomicAdd(&s_bins[w][i3], 1);
    }
    __syncthreads();
    if (t < 100) {
        int s = 0;
        #pragma unroll
        for (int k = 0; k < 8; k++) s += s_bins[k][t];
        int b = r / 3, c = r % 3;
        atomicAdd(&g_concat[b * CONC + EMB + c * 100 + t], (float)s);
    }
}

// ============ mid GEMM: out[b,n] += in[b,:].Wt[n,:] (fine K-split atomics) ============
__global__ __launch_bounds__(256) void mid_gemm(const float* __restrict__ in, int istride, int Kfull,
                                                const float* __restrict__ Wt,
                                                float* __restrict__ out, int ostride, int N,
                                                int relu_in) {
    __shared__ float is[64][33];
    __shared__ float ws[64][33];
    int n0 = blockIdx.x * 64;
    int k0 = blockIdx.y * 32;
    int t = threadIdx.x;
    int tn = t & 15, tb = t >> 4;
    float acc[4][4] = {};
    #pragma unroll
    for (int e = 0; e < 8; e++) {
        int idx = t + e * 256;
        int row = idx >> 5, col = idx & 31;
        float iv = (k0 + col < Kfull) ? in[(size_t)row * istride + k0 + col] : 0.f;
        if (relu_in) iv = fmaxf(iv, 0.f);
        is[row][col] = iv;
        int n = n0 + row;
        ws[row][col] = (n < N && k0 + col < Kfull) ? Wt[(size_t)n * Kfull + k0 + col] : 0.f;
    }
    __syncthreads();
    #pragma unroll
    for (int kk = 0; kk < 32; kk++) {
        float xv[4], wv[4];
        #pragma unroll
        for (int i2 = 0; i2 < 4; i2++) xv[i2] = is[tb + 16 * i2][kk];
        #pragma unroll
        for (int j = 0; j < 4; j++) wv[j] = ws[tn + 16 * j][kk];
        #pragma unroll
        for (int i2 = 0; i2 < 4; i2++)
            #pragma unroll
            for (int j = 0; j < 4; j++) acc[i2][j] += xv[i2] * wv[j];
    }
    #pragma unroll
    for (int i2 = 0; i2 < 4; i2++) {
        int b = tb + 16 * i2;
        #pragma unroll
        for (int j = 0; j < 4; j++) {
            int n = n0 + tn + 16 * j;
            if (n < N) atomicAdd(&out[(size_t)b * ostride + n], acc[i2][j]);
        }
    }
}

// ============ merged head layer-1: g_hid[b,n] += relu(g_h[b,:]).W(n)[.,:] ============
__global__ __launch_bounds__(256) void heads1_gemm(const float* __restrict__ stW1,
                                                   const float* __restrict__ ageW1,
                                                   const float* __restrict__ genW1) {
    __shared__ float is[64][33];
    __shared__ float ws[64][33];
    int n0 = blockIdx.x * 64;
    int k0 = blockIdx.y * 32;
    int t = threadIdx.x;
    int tn = t & 15, tb = t >> 4;
    #pragma unroll
    for (int e = 0; e < 8; e++) {
        int idx = t + e * 256;
        int row = idx >> 5, col = idx & 31;
        float iv = (k0 + col < HID) ? fmaxf(g_h[(size_t)row * HID + k0 + col], 0.f) : 0.f;
        is[row][col] = iv;
        int n = n0 + row;
        float wv = 0.f;
        if (n < 1400 && k0 + col < HID) {
            const float* p = (n < 600) ? (stW1 + (size_t)n * HID)
                           : (n < 1000) ? (ageW1 + (size_t)(n - 600) * HID)
                                        : (genW1 + (size_t)(n - 1000) * HID);
            wv = p[k0 + col];
        }
        ws[row][col] = wv;
    }
    __syncthreads();
    float acc[4][4] = {};
    #pragma unroll
    for (int kk = 0; kk < 32; kk++) {
        float xv[4], wv[4];
        #pragma unroll
        for (int i2 = 0; i2 < 4; i2++) xv[i2] = is[tb + 16 * i2][kk];
        #pragma unroll
        for (int j = 0; j < 4; j++) wv[j] = ws[tn + 16 * j][kk];
        #pragma unroll
        for (int i2 = 0; i2 < 4; i2++)
            #pragma unroll
            for (int j = 0; j < 4; j++) acc[i2][j] += xv[i2] * wv[j];
    }
    #pragma unroll
    for (int i2 = 0; i2 < 4; i2++) {
        int b = tb + 16 * i2;
        #pragma unroll
        for (int j = 0; j < 4; j++) {
            int n = n0 + tn + 16 * j;
            if (n < 1400) atomicAdd(&g_hid[(size_t)b * 1400 + n], acc[i2][j]);
        }
    }
}

// ================= fused heads: relu(hid) -> 16 logits + relu + 3 softmaxes =================
__global__ __launch_bounds__(256) void heads_kernel(const float* __restrict__ stW2, const float* __restrict__ stb2,
                                                    const float* __restrict__ ageW2, const float* __restrict__ ageb2,
                                                    const float* __restrict__ genW2, const float* __restrict__ genb2,
                                                    float* __restrict__ out) {
    int b = blockIdx.x;
    __shared__ float sh[1400];
    __shared__ float slog[16];
    int t = threadIdx.x;
    for (int i = t; i < 1400; i += 256) sh[i] = fmaxf(g_hid[b * 1400 + i], 0.f);
    __syncthreads();
    int w = t >> 5, lane = t & 31;
    for (int l = w; l < 16; l += 8) {
        const float* wr; const float* basep; int len; float bv;
        if (l < 10)      { wr = stW2  + l * 600;        basep = sh;        len = 600; bv = stb2[l]; }
        else if (l < 14) { wr = ageW2 + (l - 10) * 400; basep = sh + 600;  len = 400; bv = ageb2[l - 10]; }
        else             { wr = genW2 + (l - 14) * 400; basep = sh + 1000; len = 400; bv = genb2[l - 14]; }
        float s = 0.f;
        for (int i = lane; i < len; i += 32) s += basep[i] * wr[i];
        for (int o = 16; o > 0; o >>= 1) s += __shfl_xor_sync(0xffffffffu, s, o);
        if (lane == 0) slog[l] = fmaxf(s + bv, 0.f);
    }
    __syncthreads();
    if (t == 0) {
        float m = slog[0];
        for (int i = 1; i < 10; i++) m = fmaxf(m, slog[i]);
        float e[10], sum = 0.f;
        for (int i = 0; i < 10; i++) { e[i] = expf(slog[i] - m); sum += e[i]; }
        for (int i = 0; i < 10; i++) out[b * 10 + i] = e[i] / sum;
    } else if (t == 32) {
        float m = slog[10];
        for (int i = 11; i < 14; i++) m = fmaxf(m, slog[i]);
        float e[4], sum = 0.f;
        for (int i = 0; i < 4; i++) { e[i] = expf(slog[10 + i] - m); sum += e[i]; }
        for (int i = 0; i < 4; i++) out[640 + b * 4 + i] = e[i] / sum;
    } else if (t == 64) {
        float m = fmaxf(slog[14], slog[15]);
        float e0 = expf(slog[14] - m), e1 = expf(slog[15] - m);
        float inv = 1.f / (e0 + e1);
        out[896 + b * 2]     = e0 * inv;
        out[896 + b * 2 + 1] = e1 * inv;
    }
}

extern "C" void kernel_launch(void* const* d_in, const int* in_sizes, int n_in,
                              void* d_out, int out_size) {
    const float* x      = (const float*)d_in[0];
    const float* base_W = (const float*)d_in[1];
    const float* base_b = (const float*)d_in[2];
    const float* hW     = (const float*)d_in[3];
    const float* hb     = (const float*)d_in[4];
    const float* stW1   = (const float*)d_in[5];
    const float* stb1   = (const float*)d_in[6];
    const float* stW2   = (const float*)d_in[7];
    const float* stb2   = (const float*)d_in[8];
    const float* ageW1  = (const float*)d_in[9];
    const float* ageb1  = (const float*)d_in[10];
    const float* ageW2  = (const float*)d_in[11];
    const float* ageb2  = (const float*)d_in[12];
    const float* genW1  = (const float*)d_in[13];
    const float* genb1  = (const float*)d_in[14];
    const float* genW2  = (const float*)d_in[15];
    const float* genb2  = (const float*)d_in[16];
    float* out = (float*)d_out;

    float *pc = nullptr, *ph = nullptr;
    cudaGetSymbolAddress((void**)&pc, g_concat);
    cudaGetSymbolAddress((void**)&ph, g_h);

    cudaFuncSetAttribute(gemm1, cudaFuncAttributeMaxDynamicSharedMemorySize, G1_SMEM);

    init_all<<<(INIT_TOTAL + 255) / 256, 256>>>(base_b, hb, stb1, ageb1, genb1);
    hist_minmax<<<BB * CHN * 4, 256>>>(x);
    hist_bins<<<BB * CHN * 4, 256>>>(x);
    gemm1<<<dim3(2, KSPLIT), 384, G1_SMEM>>>(x, base_W);

    mid_gemm<<<dim3(7, 26), 256>>>(pc, CONC, CONC, hW, ph, HID, HID, 0);
    heads1_gemm<<<dim3(22, 13), 256>>>(stW1, ageW1, genW1);
    heads_kernel<<<BB, 256>>>(stW2, stb2, ageW2, ageb2, genW2, genb2, out);
}

// round 16
// speedup vs baseline: 1.0409x; 1.0409x over previous
#include <cuda_runtime.h>
#include <cstdint>

#define BB   64
#define CHN  3
#define HWP  (224*224)
#define KBIG (CHN*HWP)
#define EMB  512
#define CONC 812
#define HID  400

__device__ float g_concat[BB*CONC];     // [64][812]: xm | hist
__device__ float g_h[BB*HID];           // [64][400] pre-activation
__device__ float g_hid[BB*1400];        // [64][600|400|400] pre-activation
__device__ unsigned g_mm[BB*CHN*2];     // per-(b,c) min/max as monotone keys

__device__ __forceinline__ uint32_t smem_u32(const void* p) {
    uint32_t a;
    asm("{ .reg .u64 t; cvta.to.shared.u64 t, %1; cvt.u32.u64 %0, t; }" : "=r"(a) : "l"(p));
    return a;
}

__device__ __forceinline__ void ldm4(uint32_t* r, uint32_t addr) {
    asm volatile("ldmatrix.sync.aligned.m8n8.x4.shared.b16 {%0,%1,%2,%3}, [%4];"
        : "=r"(r[0]), "=r"(r[1]), "=r"(r[2]), "=r"(r[3]) : "r"(addr));
}

__device__ __forceinline__ void mma16816(float* d, const uint32_t* a, const uint32_t* b) {
    asm volatile("mma.sync.aligned.m16n8k16.row.col.f32.bf16.bf16.f32 "
        "{%0,%1,%2,%3}, {%4,%5,%6,%7}, {%8,%9}, {%0,%1,%2,%3};"
        : "+f"(d[0]), "+f"(d[1]), "+f"(d[2]), "+f"(d[3])
        : "r"(a[0]), "r"(a[1]), "r"(a[2]), "r"(a[3]), "r"(b[0]), "r"(b[1]));
}

// split fp32x4 -> bf16 hi pair + bf16 lo pair (low halfword = lower k)
__device__ __forceinline__ void cvt_split(float4 v, uint32_t& h01, uint32_t& h23,
                                          uint32_t& l01, uint32_t& l23) {
    asm("cvt.rn.bf16x2.f32 %0, %1, %2;" : "=r"(h01) : "f"(v.y), "f"(v.x));
    asm("cvt.rn.bf16x2.f32 %0, %1, %2;" : "=r"(h23) : "f"(v.w), "f"(v.z));
    float r0 = v.x - __uint_as_float(h01 << 16);
    float r1 = v.y - __uint_as_float(h01 & 0xffff0000u);
    float r2 = v.z - __uint_as_float(h23 << 16);
    float r3 = v.w - __uint_as_float(h23 & 0xffff0000u);
    asm("cvt.rn.bf16x2.f32 %0, %1, %2;" : "=r"(l01) : "f"(r1), "f"(r0));
    asm("cvt.rn.bf16x2.f32 %0, %1, %2;" : "=r"(l23) : "f"(r3), "f"(r2));
}

// mbarrier helpers
__device__ __forceinline__ void mbar_init(uint32_t a, uint32_t cnt) {
    asm volatile("mbarrier.init.shared.b64 [%0], %1;" :: "r"(a), "r"(cnt) : "memory");
}
__device__ __forceinline__ void mbar_arrive(uint32_t a) {
    uint64_t st;
    asm volatile("mbarrier.arrive.shared.b64 %0, [%1];" : "=l"(st) : "r"(a) : "memory");
}
__device__ __forceinline__ void mbar_wait(uint32_t a, uint32_t parity) {
    asm volatile(
        "{\n\t.reg .pred P;\n\t"
        "WL_%=:\n\t"
        "mbarrier.try_wait.parity.acquire.cta.shared::cta.b64 P, [%0], %1, 0x989680;\n\t"
        "@P bra.uni WD_%=;\n\t"
        "bra.uni WL_%=;\n\t"
        "WD_%=:\n\t}"
        :: "r"(a), "r"(parity) : "memory");
}

// monotone key transform for float atomic min/max on uint
__device__ __forceinline__ unsigned fkey(float f) {
    unsigned b = __float_as_uint(f);
    return (b & 0x80000000u) ? ~b : (b | 0x80000000u);
}
__device__ __forceinline__ float funkey(unsigned k) {
    unsigned b = (k & 0x80000000u) ? (k & 0x7fffffffu) : ~k;
    return __uint_as_float(b);
}

// ===== big GEMM: concat[b,n] += x[b,:].W[n,:]  (bf16 3-term split, HMMA) =====
// Warp-specialized, 64m x 256n CTA tile, KT=64, 2-stage 80KB ring, 1 CTA/SM.
// Producer chunk-pipelined: x + 3 W-chunk register buffers in flight.
#define KSPLIT 74
#define BUFSZ  81920    // x hi 8K | x lo 8K | W hi 32K | W lo 32K
#define G1_SMEM (2 * BUFSZ + 64)

__global__ __launch_bounds__(384, 1) void gemm1(const float* __restrict__ x,
                                                const float* __restrict__ W) {
    extern __shared__ __align__(128) uint8_t smraw[];
    uint32_t base = smem_u32(smraw);
    uint32_t MB = base + 2 * BUFSZ;           // full[0],full[1],empty[0],empty[1]

    int tid = threadIdx.x, wid = tid >> 5, lane = tid & 31;
    int n0 = blockIdx.x * 256;
    int ky = blockIdx.y;
    int t0 = ky * 31 + (ky < 58 ? ky : 58);
    int cnt = 31 + (ky < 58 ? 1 : 0);

    if (tid == 0) {
        mbar_init(MB + 0, 128);   // full[0]
        mbar_init(MB + 8, 128);   // full[1]
        mbar_init(MB + 16, 256);  // empty[0]
        mbar_init(MB + 24, 256);  // empty[1]
    }
    __syncthreads();

    if (wid >= 8) {
        // ---------------- producers (warps 8-11, 128 threads) ----------------
        int p = tid - 256;
        int prow = p >> 4, pc4 = p & 15;
        const float* xbase = x + (size_t)prow * KBIG + pc4 * 4;
        const float* wbase = W + (size_t)(n0 + prow) * KBIG + pc4 * 4;
        uint32_t swz = (uint32_t)((pc4 * 8) ^ ((prow & 7) << 4));

        float4 vx[8], vw[3][8];

#define P_LDX(T) do { size_t k0_ = (size_t)(T) * 64;                                   \
        _Pragma("unroll") for (int j = 0; j < 8; j++)                                  \
            vx[j] = *(const float4*)(xbase + (size_t)(j * 8) * KBIG + k0_); } while (0)

#define P_LDW(T, C, B) do { size_t k0_ = (size_t)(T) * 64;                             \
        _Pragma("unroll") for (int j = 0; j < 8; j++)                                  \
            vw[B][j] = *(const float4*)(wbase + (size_t)(((C) * 8 + j) * 8) * KBIG + k0_); } while (0)

#define P_STX(S) do {                                                                  \
        uint32_t bb_ = base + (S) * BUFSZ;                                             \
        uint32_t XHI = bb_, XLO = bb_ + 8192;                                          \
        _Pragma("unroll") for (int j = 0; j < 8; j++) {                                \
            uint32_t off = (uint32_t)((prow + j * 8) * 128) + swz;                     \
            uint32_t h01, h23, l01, l23;                                               \
            cvt_split(vx[j], h01, h23, l01, l23);                                      \
            asm volatile("st.shared.v2.b32 [%0], {%1, %2};" :: "r"(XHI + off), "r"(h01), "r"(h23)); \
            asm volatile("st.shared.v2.b32 [%0], {%1, %2};" :: "r"(XLO + off), "r"(l01), "r"(l23)); \
        } } while (0)

#define P_STW(S, C, B) do {                                                            \
        uint32_t bb_ = base + (S) * BUFSZ;                                             \
        uint32_t WHI = bb_ + 16384, WLO = bb_ + 49152;                                 \
        _Pragma("unroll") for (int j = 0; j < 8; j++) {                                \
            uint32_t off = (uint32_t)((prow + ((C) * 8 + j) * 8) * 128) + swz;         \
            uint32_t h01, h23, l01, l23;                                               \
            cvt_split(vw[B][j], h01, h23, l01, l23);                                   \
            asm volatile("st.shared.v2.b32 [%0], {%1, %2};" :: "r"(WHI + off), "r"(h01), "r"(h23)); \
            asm volatile("st.shared.v2.b32 [%0], {%1, %2};" :: "r"(WLO + off), "r"(l01), "r"(l23)); \
        } } while (0)

        // prologue: tile 0's x and W chunks 0-2 in flight
        P_LDX(t0); P_LDW(t0, 0, 0); P_LDW(t0, 1, 1); P_LDW(t0, 2, 2);

        int phE0 = 0, phE1 = 0;
        for (int it = 0; it < cnt; ++it) {
            int s = it & 1;
            if (it >= 2) {
                if (s == 0) { mbar_wait(MB + 16, phE0); phE0 ^= 1; }
                else        { mbar_wait(MB + 24, phE1); phE1 ^= 1; }
            }
            P_STX(s);
            P_STW(s, 0, 0);
            P_LDW(t0 + it, 3, 0);     // chunk 3 into freed buf0; latency hidden behind STS w1,w2
            P_STW(s, 1, 1);
            P_STW(s, 2, 2);
            P_STW(s, 3, 0);
            mbar_arrive(MB + s * 8);  // full[s]
            if (it + 1 < cnt) {       // next tile's loads issue now; latency absorbed by
                P_LDX(t0 + it + 1);   // next empty-wait + first STS phases
                P_LDW(t0 + it + 1, 0, 0);
                P_LDW(t0 + it + 1, 1, 1);
                P_LDW(t0 + it + 1, 2, 2);
            }
        }
        return;
    }

    // ---------------- consumers (warps 0-7): 32m x 64n each ----------------
    int warp_m = wid >> 2;
    int warp_n = wid & 3;
    int ar = lane & 7, ag = lane >> 3;
    int a_row_off = (ag & 1) * 8 + ar;
    int a_col_off = (ag >> 1) * 16;
    int b_row_off = (ag >> 1) * 8 + ar;
    int b_col_off = (ag & 1) * 16;

    float acc[2][8][4];
    #pragma unroll
    for (int i = 0; i < 2; i++)
        #pragma unroll
        for (int j = 0; j < 8; j++)
            #pragma unroll
            for (int q = 0; q < 4; q++) acc[i][j][q] = 0.f;

    int phF0 = 0, phF1 = 0;
    for (int it = 0; it < cnt; ++it) {
        int s = it & 1;
        if (s == 0) { mbar_wait(MB + 0, phF0); phF0 ^= 1; }
        else        { mbar_wait(MB + 8, phF1); phF1 ^= 1; }
        uint32_t bb_ = base + s * BUFSZ;
        uint32_t XHI = bb_, XLO = bb_ + 8192, WHI = bb_ + 16384, WLO = bb_ + 49152;
        #pragma unroll
        for (int ks = 0; ks < 4; ++ks) {
            int cbase = ks * 32;
            uint32_t ah[2][4], al[2][4], bh[4][4], bl[4][4];
            #pragma unroll
            for (int mi = 0; mi < 2; mi++) {
                int r = warp_m * 32 + mi * 16 + a_row_off;
                uint32_t col = (uint32_t)(cbase + a_col_off) ^ ((r & 7) << 4);
                ldm4(ah[mi], XHI + r * 128 + col);
                ldm4(al[mi], XLO + r * 128 + col);
            }
            #pragma unroll
            for (int ni = 0; ni < 4; ni++) {
                int r = warp_n * 64 + ni * 16 + b_row_off;
                uint32_t col = (uint32_t)(cbase + b_col_off) ^ ((r & 7) << 4);
                ldm4(bh[ni], WHI + r * 128 + col);
                ldm4(bl[ni], WLO + r * 128 + col);
            }
            if (ks == 3) mbar_arrive(MB + 16 + s * 8);   // early empty[s]: all smem reads done
            #pragma unroll
            for (int mi = 0; mi < 2; mi++)
                #pragma unroll
                for (int ni = 0; ni < 4; ni++)
                    #pragma unroll
                    for (int nj = 0; nj < 2; nj++) {
                        float* d = acc[mi][ni * 2 + nj];
                        mma16816(d, ah[mi], bh[ni] + nj * 2);
                        mma16816(d, ah[mi], bl[ni] + nj * 2);
                        mma16816(d, al[mi], bh[ni] + nj * 2);
                    }
        }
    }

    #pragma unroll
    for (int mi = 0; mi < 2; mi++) {
        int b = warp_m * 32 + mi * 16 + (lane >> 2);
        #pragma unroll
        for (int g = 0; g < 8; g++) {
            int n = n0 + warp_n * 64 + (g >> 1) * 16 + (g & 1) * 8 + (lane & 3) * 2;
            atomicAdd(&g_concat[b * CONC + n],           acc[mi][g][0]);
            atomicAdd(&g_concat[b * CONC + n + 1],       acc[mi][g][1]);
            atomicAdd(&g_concat[(b + 8) * CONC + n],     acc[mi][g][2]);
            atomicAdd(&g_concat[(b + 8) * CONC + n + 1], acc[mi][g][3]);
        }
    }
}

// ======================= merged init =======================
#define INIT_TOTAL (32768 + 25600 + 89600 + 19200 + 384)
__global__ void init_all(const float* __restrict__ bb, const float* __restrict__ hb,
                         const float* __restrict__ stb1, const float* __restrict__ ageb1,
                         const float* __restrict__ genb1) {
    int i = blockIdx.x * 256 + threadIdx.x;
    if (i < 32768) { g_concat[(i >> 9) * CONC + (i & 511)] = bb[i & 511]; return; }
    i -= 32768;
    if (i < 25600) { g_h[i] = hb[i % HID]; return; }
    i -= 25600;
    if (i < 89600) {
        int c = i % 1400;
        g_hid[i] = (c < 600) ? stb1[c] : (c < 1000 ? ageb1[c - 600] : genb1[c - 1000]);
        return;
    }
    i -= 89600;
    if (i < 19200) {
        int b = i / 300, c = i % 300;
        g_concat[b * CONC + EMB + c] = 0.f;
        return;
    }
    i -= 19200;
    if (i < 384) g_mm[i] = (i & 1) ? 0u : 0xFFFFFFFFu;
}

// ============ hist pass 1: min/max, 4 CTAs per (b,c) row ============
#define SEG (HWP / 4)
__global__ __launch_bounds__(256) void hist_minmax(const float* __restrict__ x) {
    int r = blockIdx.x >> 2, seg = blockIdx.x & 3;
    const float4* rg = (const float4*)(x + (size_t)r * HWP + (size_t)seg * SEG);
    __shared__ unsigned s_red[16];
    int t = threadIdx.x, w = t >> 5, lane = t & 31;
    float mn = 1e30f, mx = -1e30f;
    for (int i = t; i < SEG / 4; i += 256) {
        float4 v = rg[i];
        mn = fminf(mn, fminf(fminf(v.x, v.y), fminf(v.z, v.w)));
        mx = fmaxf(mx, fmaxf(fmaxf(v.x, v.y), fmaxf(v.z, v.w)));
    }
    for (int o = 16; o > 0; o >>= 1) {
        mn = fminf(mn, __shfl_xor_sync(0xffffffffu, mn, o));
        mx = fmaxf(mx, __shfl_xor_sync(0xffffffffu, mx, o));
    }
    if (lane == 0) { s_red[w] = fkey(mn); s_red[8 + w] = fkey(mx); }
    __syncthreads();
    if (t == 0) {
        unsigned a = s_red[0], b = s_red[8];
        for (int k = 1; k < 8; k++) { a = min(a, s_red[k]); b = max(b, s_red[8 + k]); }
        atomicMin(&g_mm[r * 2], a);
        atomicMax(&g_mm[r * 2 + 1], b);
    }
}

// ============ hist pass 2: binning, 4 CTAs per row ============
__global__ __launch_bounds__(256) void hist_bins(const float* __restrict__ x) {
    int r = blockIdx.x >> 2, seg = blockIdx.x & 3;
    const float4* rg = (const float4*)(x + (size_t)r * HWP + (size_t)seg * SEG);
    __shared__ int s_bins[8][100];
    int t = threadIdx.x, w = t >> 5;
    for (int i = t; i < 800; i += 256) s_bins[0][i] = 0;
    __syncthreads();
    float mnv = funkey(g_mm[r * 2]);
    float mxv = funkey(g_mm[r * 2 + 1]);
    float width = (mxv > mnv) ? (mxv - mnv) : 1.0f;
    for (int i = t; i < SEG / 4; i += 256) {
        float4 v = rg[i];
        int i0 = (int)floorf((v.x - mnv) / width * 100.0f);
        int i1 = (int)floorf((v.y - mnv) / width * 100.0f);
        int i2 = (int)floorf((v.z - mnv) / width * 100.0f);
        int i3 = (int)floorf((v.w - mnv) / width * 100.0f);
        i0 = min(max(i0, 0), 99); i1 = min(max(i1, 0), 99);
        i2 = min(max(i2, 0), 99); i3 = min(max(i3, 0), 99);
        atomicAdd(&s_bins[w][i0], 1);
        atomicAdd(&s_bins[w][i1], 1);
        atomicAdd(&s_bins[w][i2], 1);
        atomicAdd(&s_bins[w][i3], 1);
    }
    __syncthreads();
    if (t < 100) {
        int s = 0;
        #pragma unroll
        for (int k = 0; k < 8; k++) s += s_bins[k][t];
        int b = r / 3, c = r % 3;
        atomicAdd(&g_concat[b * CONC + EMB + c * 100 + t], (float)s);
    }
}

// ============ mid GEMM: out[b,n] += in[b,:].Wt[n,:] (fine K-split atomics) ============
__global__ __launch_bounds__(256) void mid_gemm(const float* __restrict__ in, int istride, int Kfull,
                                                const float* __restrict__ Wt,
                                                float* __restrict__ out, int ostride, int N,
                                                int relu_in) {
    __shared__ float is[64][33];
    __shared__ float ws[64][33];
    int n0 = blockIdx.x * 64;
    int k0 = blockIdx.y * 32;
    int t = threadIdx.x;
    int tn = t & 15, tb = t >> 4;
    float acc[4][4] = {};
    #pragma unroll
    for (int e = 0; e < 8; e++) {
        int idx = t + e * 256;
        int row = idx >> 5, col = idx & 31;
        float iv = (k0 + col < Kfull) ? in[(size_t)row * istride + k0 + col] : 0.f;
        if (relu_in) iv = fmaxf(iv, 0.f);
        is[row][col] = iv;
        int n = n0 + row;
        ws[row][col] = (n < N && k0 + col < Kfull) ? Wt[(size_t)n * Kfull + k0 + col] : 0.f;
    }
    __syncthreads();
    #pragma unroll
    for (int kk = 0; kk < 32; kk++) {
        float xv[4], wv[4];
        #pragma unroll
        for (int i2 = 0; i2 < 4; i2++) xv[i2] = is[tb + 16 * i2][kk];
        #pragma unroll
        for (int j = 0; j < 4; j++) wv[j] = ws[tn + 16 * j][kk];
        #pragma unroll
        for (int i2 = 0; i2 < 4; i2++)
            #pragma unroll
            for (int j = 0; j < 4; j++) acc[i2][j] += xv[i2] * wv[j];
    }
    #pragma unroll
    for (int i2 = 0; i2 < 4; i2++) {
        int b = tb + 16 * i2;
        #pragma unroll
        for (int j = 0; j < 4; j++) {
            int n = n0 + tn + 16 * j;
            if (n < N) atomicAdd(&out[(size_t)b * ostride + n], acc[i2][j]);
        }
    }
}

// ============ merged head layer-1: g_hid[b,n] += relu(g_h[b,:]).W(n)[.,:] ============
__global__ __launch_bounds__(256) void heads1_gemm(const float* __restrict__ stW1,
                                                   const float* __restrict__ ageW1,
                                                   const float* __restrict__ genW1) {
    __shared__ float is[64][33];
    __shared__ float ws[64][33];
    int n0 = blockIdx.x * 64;
    int k0 = blockIdx.y * 32;
    int t = threadIdx.x;
    int tn = t & 15, tb = t >> 4;
    #pragma unroll
    for (int e = 0; e < 8; e++) {
        int idx = t + e * 256;
        int row = idx >> 5, col = idx & 31;
        float iv = (k0 + col < HID) ? fmaxf(g_h[(size_t)row * HID + k0 + col], 0.f) : 0.f;
        is[row][col] = iv;
        int n = n0 + row;
        float wv = 0.f;
        if (n < 1400 && k0 + col < HID) {
            const float* p = (n < 600) ? (stW1 + (size_t)n * HID)
                           : (n < 1000) ? (ageW1 + (size_t)(n - 600) * HID)
                                        : (genW1 + (size_t)(n - 1000) * HID);
            wv = p[k0 + col];
        }
        ws[row][col] = wv;
    }
    __syncthreads();
    float acc[4][4] = {};
    #pragma unroll
    for (int kk = 0; kk < 32; kk++) {
        float xv[4], wv[4];
        #pragma unroll
        for (int i2 = 0; i2 < 4; i2++) xv[i2] = is[tb + 16 * i2][kk];
        #pragma unroll
        for (int j = 0; j < 4; j++) wv[j] = ws[tn + 16 * j][kk];
        #pragma unroll
        for (int i2 = 0; i2 < 4; i2++)
            #pragma unroll
            for (int j = 0; j < 4; j++) acc[i2][j] += xv[i2] * wv[j];
    }
    #pragma unroll
    for (int i2 = 0; i2 < 4; i2++) {
        int b = tb + 16 * i2;
        #pragma unroll
        for (int j = 0; j < 4; j++) {
            int n = n0 + tn + 16 * j;
            if (n < 1400) atomicAdd(&g_hid[(size_t)b * 1400 + n], acc[i2][j]);
        }
    }
}

// ================= fused heads: relu(hid) -> 16 logits + relu + 3 softmaxes =================
__global__ __launch_bounds__(256) void heads_kernel(const float* __restrict__ stW2, const float* __restrict__ stb2,
                                                    const float* __restrict__ ageW2, const float* __restrict__ ageb2,
                                                    const float* __restrict__ genW2, const float* __restrict__ genb2,
                                                    float* __restrict__ out) {
    int b = blockIdx.x;
    __shared__ float sh[1400];
    __shared__ float slog[16];
    int t = threadIdx.x;
    for (int i = t; i < 1400; i += 256) sh[i] = fmaxf(g_hid[b * 1400 + i], 0.f);
    __syncthreads();
    int w = t >> 5, lane = t & 31;
    for (int l = w; l < 16; l += 8) {
        const float* wr; const float* basep; int len; float bv;
        if (l < 10)      { wr = stW2  + l * 600;        basep = sh;        len = 600; bv = stb2[l]; }
        else if (l < 14) { wr = ageW2 + (l - 10) * 400; basep = sh + 600;  len = 400; bv = ageb2[l - 10]; }
        else             { wr = genW2 + (l - 14) * 400; basep = sh + 1000; len = 400; bv = genb2[l - 14]; }
        float s = 0.f;
        for (int i = lane; i < len; i += 32) s += basep[i] * wr[i];
        for (int o = 16; o > 0; o >>= 1) s += __shfl_xor_sync(0xffffffffu, s, o);
        if (lane == 0) slog[l] = fmaxf(s + bv, 0.f);
    }
    __syncthreads();
    if (t == 0) {
        float m = slog[0];
        for (int i = 1; i < 10; i++) m = fmaxf(m, slog[i]);
        float e[10], sum = 0.f;
        for (int i = 0; i < 10; i++) { e[i] = expf(slog[i] - m); sum += e[i]; }
        for (int i = 0; i < 10; i++) out[b * 10 + i] = e[i] / sum;
    } else if (t == 32) {
        float m = slog[10];
        for (int i = 11; i < 14; i++) m = fmaxf(m, slog[i]);
        float e[4], sum = 0.f;
        for (int i = 0; i < 4; i++) { e[i] = expf(slog[10 + i] - m); sum += e[i]; }
        for (int i = 0; i < 4; i++) out[640 + b * 4 + i] = e[i] / sum;
    } else if (t == 64) {
        float m = fmaxf(slog[14], slog[15]);
        float e0 = expf(slog[14] - m), e1 = expf(slog[15] - m);
        float inv = 1.f / (e0 + e1);
        out[896 + b * 2]     = e0 * inv;
        out[896 + b * 2 + 1] = e1 * inv;
    }
}

extern "C" void kernel_launch(void* const* d_in, const int* in_sizes, int n_in,
                              void* d_out, int out_size) {
    const float* x      = (const float*)d_in[0];
    const float* base_W = (const float*)d_in[1];
    const float* base_b = (const float*)d_in[2];
    const float* hW     = (const float*)d_in[3];
    const float* hb     = (const float*)d_in[4];
    const float* stW1   = (const float*)d_in[5];
    const float* stb1   = (const float*)d_in[6];
    const float* stW2   = (const float*)d_in[7];
    const float* stb2   = (const float*)d_in[8];
    const float* ageW1  = (const float*)d_in[9];
    const float* ageb1  = (const float*)d_in[10];
    const float* ageW2  = (const float*)d_in[11];
    const float* ageb2  = (const float*)d_in[12];
    const float* genW1  = (const float*)d_in[13];
    const float* genb1  = (const float*)d_in[14];
    const float* genW2  = (const float*)d_in[15];
    const float* genb2  = (const float*)d_in[16];
    float* out = (float*)d_out;

    float *pc = nullptr, *ph = nullptr;
    cudaGetSymbolAddress((void**)&pc, g_concat);
    cudaGetSymbolAddress((void**)&ph, g_h);

    cudaFuncSetAttribute(gemm1, cudaFuncAttributeMaxDynamicSharedMemorySize, G1_SMEM);

    init_all<<<(INIT_TOTAL + 255) / 256, 256>>>(base_b, hb, stb1, ageb1, genb1);
    hist_minmax<<<BB * CHN * 4, 256>>>(x);
    hist_bins<<<BB * CHN * 4, 256>>>(x);
    gemm1<<<dim3(2, KSPLIT), 384, G1_SMEM>>>(x, base_W);

    mid_gemm<<<dim3(7, 26), 256>>>(pc, CONC, CONC, hW, ph, HID, HID, 0);
    heads1_gemm<<<dim3(22, 13), 256>>>(stW1, ageW1, genW1);
    heads_kernel<<<BB, 256>>>(stW2, stb2, ageW2, ageb2, genW2, genb2, out);
}

// round 17
// speedup vs baseline: 1.0987x; 1.0555x over previous
#include <cuda_runtime.h>
#include <cuda_fp16.h>
#include <cstdint>

#define BB   64
#define CHN  3
#define HWP  (224*224)
#define KBIG (CHN*HWP)
#define EMB  512
#define CONC 812
#define HID  400

__device__ float g_concat[BB*CONC];     // [64][812]: xm | hist
__device__ float g_h[BB*HID];           // [64][400] pre-activation
__device__ float g_hid[BB*1400];        // [64][600|400|400] pre-activation
__device__ unsigned g_mm[BB*CHN*2];     // per-(b,c) min/max as monotone keys

__device__ __forceinline__ uint32_t smem_u32(const void* p) {
    uint32_t a;
    asm("{ .reg .u64 t; cvta.to.shared.u64 t, %1; cvt.u32.u64 %0, t; }" : "=r"(a) : "l"(p));
    return a;
}

__device__ __forceinline__ void ldm4(uint32_t* r, uint32_t addr) {
    asm volatile("ldmatrix.sync.aligned.m8n8.x4.shared.b16 {%0,%1,%2,%3}, [%4];"
        : "=r"(r[0]), "=r"(r[1]), "=r"(r[2]), "=r"(r[3]) : "r"(addr));
}

__device__ __forceinline__ void mma16816h(float* d, const uint32_t* a, const uint32_t* b) {
    asm volatile("mma.sync.aligned.m16n8k16.row.col.f32.f16.f16.f32 "
        "{%0,%1,%2,%3}, {%4,%5,%6,%7}, {%8,%9}, {%0,%1,%2,%3};"
        : "+f"(d[0]), "+f"(d[1]), "+f"(d[2]), "+f"(d[3])
        : "r"(a[0]), "r"(a[1]), "r"(a[2]), "r"(a[3]), "r"(b[0]), "r"(b[1]));
}

// fp32x4 -> fp16 hi pairs + fp16 residual pairs (low halfword = lower k)
__device__ __forceinline__ void cvt_split_h(float4 v, uint32_t& h01, uint32_t& h23,
                                            uint32_t& l01, uint32_t& l23) {
    __half2 a = __float22half2_rn(make_float2(v.x, v.y));
    __half2 b = __float22half2_rn(make_float2(v.z, v.w));
    float2 af = __half22float2(a), bf = __half22float2(b);
    __half2 ar = __float22half2_rn(make_float2(v.x - af.x, v.y - af.y));
    __half2 br = __float22half2_rn(make_float2(v.z - bf.x, v.w - bf.y));
    h01 = *(uint32_t*)&a; h23 = *(uint32_t*)&b;
    l01 = *(uint32_t*)&ar; l23 = *(uint32_t*)&br;
}
// fp32x4 -> fp16 pairs (hi only)
__device__ __forceinline__ void cvt_h(float4 v, uint32_t& h01, uint32_t& h23) {
    __half2 a = __float22half2_rn(make_float2(v.x, v.y));
    __half2 b = __float22half2_rn(make_float2(v.z, v.w));
    h01 = *(uint32_t*)&a; h23 = *(uint32_t*)&b;
}

// mbarrier helpers
__device__ __forceinline__ void mbar_init(uint32_t a, uint32_t cnt) {
    asm volatile("mbarrier.init.shared.b64 [%0], %1;" :: "r"(a), "r"(cnt) : "memory");
}
__device__ __forceinline__ void mbar_arrive(uint32_t a) {
    uint64_t st;
    asm volatile("mbarrier.arrive.shared.b64 %0, [%1];" : "=l"(st) : "r"(a) : "memory");
}
__device__ __forceinline__ void mbar_wait(uint32_t a, uint32_t parity) {
    asm volatile(
        "{\n\t.reg .pred P;\n\t"
        "WL_%=:\n\t"
        "mbarrier.try_wait.parity.acquire.cta.shared::cta.b64 P, [%0], %1, 0x989680;\n\t"
        "@P bra.uni WD_%=;\n\t"
        "bra.uni WL_%=;\n\t"
        "WD_%=:\n\t}"
        :: "r"(a), "r"(parity) : "memory");
}

// monotone key transform for float atomic min/max on uint
__device__ __forceinline__ unsigned fkey(float f) {
    unsigned b = __float_as_uint(f);
    return (b & 0x80000000u) ? ~b : (b | 0x80000000u);
}
__device__ __forceinline__ float funkey(unsigned k) {
    unsigned b = (k & 0x80000000u) ? (k & 0x7fffffffu) : ~k;
    return __uint_as_float(b);
}

// ===== big GEMM: concat[b,n] += x[b,:].W[n,:]  (fp16 2-term split, HMMA) =====
// x = xh + xl (fp16+fp16 residual); W = wh (fp16). Error == W rounded to fp16 (~2^-12).
// Warp-specialized, 64m x 256n CTA tile, KT=64, 3-stage 48KB ring, 1 CTA/SM.
#define KSPLIT 74
#define STAGES 3
#define BUFSZ  49152    // x hi 8K | x lo 8K | W hi 32K
#define G1_SMEM (STAGES * BUFSZ + 64)

__global__ __launch_bounds__(384, 1) void gemm1(const float* __restrict__ x,
                                                const float* __restrict__ W) {
    extern __shared__ __align__(128) uint8_t smraw[];
    uint32_t base = smem_u32(smraw);
    uint32_t MB = base + STAGES * BUFSZ;   // full[0..2] @ +0,8,16; empty[0..2] @ +24,32,40

    int tid = threadIdx.x, wid = tid >> 5, lane = tid & 31;
    int n0 = blockIdx.x * 256;
    int ky = blockIdx.y;
    int t0 = ky * 31 + (ky < 58 ? ky : 58);
    int cnt = 31 + (ky < 58 ? 1 : 0);

    if (tid == 0) {
        #pragma unroll
        for (int s = 0; s < STAGES; s++) {
            mbar_init(MB + s * 8, 128);        // full[s]: producer threads
            mbar_init(MB + 24 + s * 8, 256);   // empty[s]: consumer threads
        }
    }
    __syncthreads();

    if (wid >= 8) {
        // ---------------- producers (warps 8-11, 128 threads) ----------------
        int p = tid - 256;
        int prow = p >> 4, pc4 = p & 15;
        const float* xbase = x + (size_t)prow * KBIG + pc4 * 4;
        const float* wbase = W + (size_t)(n0 + prow) * KBIG + pc4 * 4;
        uint32_t swz = (uint32_t)((pc4 * 8) ^ ((prow & 7) << 4));

        float4 vx[8], vw[3][8];

#define P_LDX(T) do { size_t k0_ = (size_t)(T) * 64;                                   \
        _Pragma("unroll") for (int j = 0; j < 8; j++)                                  \
            vx[j] = *(const float4*)(xbase + (size_t)(j * 8) * KBIG + k0_); } while (0)

#define P_LDW(T, C, B) do { size_t k0_ = (size_t)(T) * 64;                             \
        _Pragma("unroll") for (int j = 0; j < 8; j++)                                  \
            vw[B][j] = *(const float4*)(wbase + (size_t)(((C) * 8 + j) * 8) * KBIG + k0_); } while (0)

#define P_STX(S) do {                                                                  \
        uint32_t bb_ = base + (S) * BUFSZ;                                             \
        uint32_t XHI = bb_, XLO = bb_ + 8192;                                          \
        _Pragma("unroll") for (int j = 0; j < 8; j++) {                                \
            uint32_t off = (uint32_t)((prow + j * 8) * 128) + swz;                     \
            uint32_t h01, h23, l01, l23;                                               \
            cvt_split_h(vx[j], h01, h23, l01, l23);                                    \
            asm volatile("st.shared.v2.b32 [%0], {%1, %2};" :: "r"(XHI + off), "r"(h01), "r"(h23)); \
            asm volatile("st.shared.v2.b32 [%0], {%1, %2};" :: "r"(XLO + off), "r"(l01), "r"(l23)); \
        } } while (0)

#define P_STW(S, C, B) do {                                                            \
        uint32_t bb_ = base + (S) * BUFSZ;                                             \
        uint32_t WHI = bb_ + 16384;                                                    \
        _Pragma("unroll") for (int j = 0; j < 8; j++) {                                \
            uint32_t off = (uint32_t)((prow + ((C) * 8 + j) * 8) * 128) + swz;         \
            uint32_t h01, h23;                                                         \
            cvt_h(vw[B][j], h01, h23);                                                 \
            asm volatile("st.shared.v2.b32 [%0], {%1, %2};" :: "r"(WHI + off), "r"(h01), "r"(h23)); \
        } } while (0)

        // prologue: tile 0's x and W chunks 0-2 in flight
        P_LDX(t0); P_LDW(t0, 0, 0); P_LDW(t0, 1, 1); P_LDW(t0, 2, 2);

        int phE[STAGES] = {0, 0, 0};
        int s = 0;
        for (int it = 0; it < cnt; ++it) {
            if (it >= STAGES) { mbar_wait(MB + 24 + s * 8, phE[s]); phE[s] ^= 1; }
            P_STX(s);
            P_STW(s, 0, 0);
            P_LDW(t0 + it, 3, 0);     // chunk 3 into freed buf0; latency behind STS w1,w2
            P_STW(s, 1, 1);
            P_STW(s, 2, 2);
            P_STW(s, 3, 0);
            mbar_arrive(MB + s * 8);  // full[s]
            if (it + 1 < cnt) {
                P_LDX(t0 + it + 1);
                P_LDW(t0 + it + 1, 0, 0);
                P_LDW(t0 + it + 1, 1, 1);
                P_LDW(t0 + it + 1, 2, 2);
            }
            if (++s == STAGES) s = 0;
        }
        return;
    }

    // ---------------- consumers (warps 0-7): 32m x 64n each ----------------
    int warp_m = wid >> 2;
    int warp_n = wid & 3;
    int ar = lane & 7, ag = lane >> 3;
    int a_row_off = (ag & 1) * 8 + ar;
    int a_col_off = (ag >> 1) * 16;
    int b_row_off = (ag >> 1) * 8 + ar;
    int b_col_off = (ag & 1) * 16;

    float acc[2][8][4];
    #pragma unroll
    for (int i = 0; i < 2; i++)
        #pragma unroll
        for (int j = 0; j < 8; j++)
            #pragma unroll
            for (int q = 0; q < 4; q++) acc[i][j][q] = 0.f;

    int phF[STAGES] = {0, 0, 0};
    int s = 0;
    for (int it = 0; it < cnt; ++it) {
        mbar_wait(MB + s * 8, phF[s]); phF[s] ^= 1;
        uint32_t bb_ = base + s * BUFSZ;
        uint32_t XHI = bb_, XLO = bb_ + 8192, WHI = bb_ + 16384;
        #pragma unroll
        for (int ks = 0; ks < 4; ++ks) {
            int cbase = ks * 32;
            uint32_t ah[2][4], al[2][4], bh[4][4];
            #pragma unroll
            for (int mi = 0; mi < 2; mi++) {
                int r = warp_m * 32 + mi * 16 + a_row_off;
                uint32_t col = (uint32_t)(cbase + a_col_off) ^ ((r & 7) << 4);
                ldm4(ah[mi], XHI + r * 128 + col);
                ldm4(al[mi], XLO + r * 128 + col);
            }
            #pragma unroll
            for (int ni = 0; ni < 4; ni++) {
                int r = warp_n * 64 + ni * 16 + b_row_off;
                uint32_t col = (uint32_t)(cbase + b_col_off) ^ ((r & 7) << 4);
                ldm4(bh[ni], WHI + r * 128 + col);
            }
            if (ks == 3) mbar_arrive(MB + 24 + s * 8);   // early empty[s]
            // term-major: 16 independent accs per pass
            #pragma unroll
            for (int mi = 0; mi < 2; mi++)
                #pragma unroll
                for (int ni = 0; ni < 4; ni++)
                    #pragma unroll
                    for (int nj = 0; nj < 2; nj++)
                        mma16816h(acc[mi][ni * 2 + nj], ah[mi], bh[ni] + nj * 2);
            #pragma unroll
            for (int mi = 0; mi < 2; mi++)
                #pragma unroll
                for (int ni = 0; ni < 4; ni++)
                    #pragma unroll
                    for (int nj = 0; nj < 2; nj++)
                        mma16816h(acc[mi][ni * 2 + nj], al[mi], bh[ni] + nj * 2);
        }
        if (++s == STAGES) s = 0;
    }

    #pragma unroll
    for (int mi = 0; mi < 2; mi++) {
        int b = warp_m * 32 + mi * 16 + (lane >> 2);
        #pragma unroll
        for (int g = 0; g < 8; g++) {
            int n = n0 + warp_n * 64 + (g >> 1) * 16 + (g & 1) * 8 + (lane & 3) * 2;
            atomicAdd(&g_concat[b * CONC + n],           acc[mi][g][0]);
            atomicAdd(&g_concat[b * CONC + n + 1],       acc[mi][g][1]);
            atomicAdd(&g_concat[(b + 8) * CONC + n],     acc[mi][g][2]);
            atomicAdd(&g_concat[(b + 8) * CONC + n + 1], acc[mi][g][3]);
        }
    }
}

// ======================= merged init =======================
#define INIT_TOTAL (32768 + 25600 + 89600 + 19200 + 384)
__global__ void init_all(const float* __restrict__ bb, const float* __restrict__ hb,
                         const float* __restrict__ stb1, const float* __restrict__ ageb1,
                         const float* __restrict__ genb1) {
    int i = blockIdx.x * 256 + threadIdx.x;
    if (i < 32768) { g_concat[(i >> 9) * CONC + (i & 511)] = bb[i & 511]; return; }
    i -= 32768;
    if (i < 25600) { g_h[i] = hb[i % HID]; return; }
    i -= 25600;
    if (i < 89600) {
        int c = i % 1400;
        g_hid[i] = (c < 600) ? stb1[c] : (c < 1000 ? ageb1[c - 600] : genb1[c - 1000]);
        return;
    }
    i -= 89600;
    if (i < 19200) {
        int b = i / 300, c = i % 300;
        g_concat[b * CONC + EMB + c] = 0.f;
        return;
    }
    i -= 19200;
    if (i < 384) g_mm[i] = (i & 1) ? 0u : 0xFFFFFFFFu;
}

// ============ hist pass 1: min/max, 4 CTAs per (b,c) row ============
#define SEG (HWP / 4)
__global__ __launch_bounds__(256) void hist_minmax(const float* __restrict__ x) {
    int r = blockIdx.x >> 2, seg = blockIdx.x & 3;
    const float4* rg = (const float4*)(x + (size_t)r * HWP + (size_t)seg * SEG);
    __shared__ unsigned s_red[16];
    int t = threadIdx.x, w = t >> 5, lane = t & 31;
    float mn = 1e30f, mx = -1e30f;
    for (int i = t; i < SEG / 4; i += 256) {
        float4 v = rg[i];
        mn = fminf(mn, fminf(fminf(v.x, v.y), fminf(v.z, v.w)));
        mx = fmaxf(mx, fmaxf(fmaxf(v.x, v.y), fmaxf(v.z, v.w)));
    }
    for (int o = 16; o > 0; o >>= 1) {
        mn = fminf(mn, __shfl_xor_sync(0xffffffffu, mn, o));
        mx = fmaxf(mx, __shfl_xor_sync(0xffffffffu, mx, o));
    }
    if (lane == 0) { s_red[w] = fkey(mn); s_red[8 + w] = fkey(mx); }
    __syncthreads();
    if (t == 0) {
        unsigned a = s_red[0], b = s_red[8];
        for (int k = 1; k < 8; k++) { a = min(a, s_red[k]); b = max(b, s_red[8 + k]); }
        atomicMin(&g_mm[r * 2], a);
        atomicMax(&g_mm[r * 2 + 1], b);
    }
}

// ============ hist pass 2: binning, 4 CTAs per row ============
__global__ __launch_bounds__(256) void hist_bins(const float* __restrict__ x) {
    int r = blockIdx.x >> 2, seg = blockIdx.x & 3;
    const float4* rg = (const float4*)(x + (size_t)r * HWP + (size_t)seg * SEG);
    __shared__ int s_bins[8][100];
    int t = threadIdx.x, w = t >> 5;
    for (int i = t; i < 800; i += 256) s_bins[0][i] = 0;
    __syncthreads();
    float mnv = funkey(g_mm[r * 2]);
    float mxv = funkey(g_mm[r * 2 + 1]);
    float width = (mxv > mnv) ? (mxv - mnv) : 1.0f;
    for (int i = t; i < SEG / 4; i += 256) {
        float4 v = rg[i];
        int i0 = (int)floorf((v.x - mnv) / width * 100.0f);
        int i1 = (int)floorf((v.y - mnv) / width * 100.0f);
        int i2 = (int)floorf((v.z - mnv) / width * 100.0f);
        int i3 = (int)floorf((v.w - mnv) / width * 100.0f);
        i0 = min(max(i0, 0), 99); i1 = min(max(i1, 0), 99);
        i2 = min(max(i2, 0), 99); i3 = min(max(i3, 0), 99);
        atomicAdd(&s_bins[w][i0], 1);
        atomicAdd(&s_bins[w][i1], 1);
        atomicAdd(&s_bins[w][i2], 1);
        atomicAdd(&s_bins[w][i3], 1);
    }
    __syncthreads();
    if (t < 100) {
        int s = 0;
        #pragma unroll
        for (int k = 0; k < 8; k++) s += s_bins[k][t];
        int b = r / 3, c = r % 3;
        atomicAdd(&g_concat[b * CONC + EMB + c * 100 + t], (float)s);
    }
}

// ============ mid GEMM: out[b,n] += in[b,:].Wt[n,:] (fine K-split atomics) ============
__global__ __launch_bounds__(256) void mid_gemm(const float* __restrict__ in, int istride, int Kfull,
                                                const float* __restrict__ Wt,
                                                float* __restrict__ out, int ostride, int N,
                                                int relu_in) {
    __shared__ float is[64][33];
    __shared__ float ws[64][33];
    int n0 = blockIdx.x * 64;
    int k0 = blockIdx.y * 32;
    int t = threadIdx.x;
    int tn = t & 15, tb = t >> 4;
    float acc[4][4] = {};
    #pragma unroll
    for (int e = 0; e < 8; e++) {
        int idx = t + e * 256;
        int row = idx >> 5, col = idx & 31;
        float iv = (k0 + col < Kfull) ? in[(size_t)row * istride + k0 + col] : 0.f;
        if (relu_in) iv = fmaxf(iv, 0.f);
        is[row][col] = iv;
        int n = n0 + row;
        ws[row][col] = (n < N && k0 + col < Kfull) ? Wt[(size_t)n * Kfull + k0 + col] : 0.f;
    }
    __syncthreads();
    #pragma unroll
    for (int kk = 0; kk < 32; kk++) {
        float xv[4], wv[4];
        #pragma unroll
        for (int i2 = 0; i2 < 4; i2++) xv[i2] = is[tb + 16 * i2][kk];
        #pragma unroll
        for (int j = 0; j < 4; j++) wv[j] = ws[tn + 16 * j][kk];
        #pragma unroll
        for (int i2 = 0; i2 < 4; i2++)
            #pragma unroll
            for (int j = 0; j < 4; j++) acc[i2][j] += xv[i2] * wv[j];
    }
    #pragma unroll
    for (int i2 = 0; i2 < 4; i2++) {
        int b = tb + 16 * i2;
        #pragma unroll
        for (int j = 0; j < 4; j++) {
            int n = n0 + tn + 16 * j;
            if (n < N) atomicAdd(&out[(size_t)b * ostride + n], acc[i2][j]);
        }
    }
}

// ============ merged head layer-1: g_hid[b,n] += relu(g_h[b,:]).W(n)[.,:] ============
__global__ __launch_bounds__(256) void heads1_gemm(const float* __restrict__ stW1,
                                                   const float* __restrict__ ageW1,
                                                   const float* __restrict__ genW1) {
    __shared__ float is[64][33];
    __shared__ float ws[64][33];
    int n0 = blockIdx.x * 64;
    int k0 = blockIdx.y * 32;
    int t = threadIdx.x;
    int tn = t & 15, tb = t >> 4;
    #pragma unroll
    for (int e = 0; e < 8; e++) {
        int idx = t + e * 256;
        int row = idx >> 5, col = idx & 31;
        float iv = (k0 + col < HID) ? fmaxf(g_h[(size_t)row * HID + k0 + col], 0.f) : 0.f;
        is[row][col] = iv;
        int n = n0 + row;
        float wv = 0.f;
        if (n < 1400 && k0 + col < HID) {
            const float* p = (n < 600) ? (stW1 + (size_t)n * HID)
                           : (n < 1000) ? (ageW1 + (size_t)(n - 600) * HID)
                                        : (genW1 + (size_t)(n - 1000) * HID);
            wv = p[k0 + col];
        }
        ws[row][col] = wv;
    }
    __syncthreads();
    float acc[4][4] = {};
    #pragma unroll
    for (int kk = 0; kk < 32; kk++) {
        float xv[4], wv[4];
        #pragma unroll
        for (int i2 = 0; i2 < 4; i2++) xv[i2] = is[tb + 16 * i2][kk];
        #pragma unroll
        for (int j = 0; j < 4; j++) wv[j] = ws[tn + 16 * j][kk];
        #pragma unroll
        for (int i2 = 0; i2 < 4; i2++)
            #pragma unroll
            for (int j = 0; j < 4; j++) acc[i2][j] += xv[i2] * wv[j];
    }
    #pragma unroll
    for (int i2 = 0; i2 < 4; i2++) {
        int b = tb + 16 * i2;
        #pragma unroll
        for (int j = 0; j < 4; j++) {
            int n = n0 + tn + 16 * j;
            if (n < 1400) atomicAdd(&g_hid[(size_t)b * 1400 + n], acc[i2][j]);
        }
    }
}

// ================= fused heads: relu(hid) -> 16 logits + relu + 3 softmaxes =================
__global__ __launch_bounds__(256) void heads_kernel(const float* __restrict__ stW2, const float* __restrict__ stb2,
                                                    const float* __restrict__ ageW2, const float* __restrict__ ageb2,
                                                    const float* __restrict__ genW2, const float* __restrict__ genb2,
                                                    float* __restrict__ out) {
    int b = blockIdx.x;
    __shared__ float sh[1400];
    __shared__ float slog[16];
    int t = threadIdx.x;
    for (int i = t; i < 1400; i += 256) sh[i] = fmaxf(g_hid[b * 1400 + i], 0.f);
    __syncthreads();
    int w = t >> 5, lane = t & 31;
    for (int l = w; l < 16; l += 8) {
        const float* wr; const float* basep; int len; float bv;
        if (l < 10)      { wr = stW2  + l * 600;        basep = sh;        len = 600; bv = stb2[l]; }
        else if (l < 14) { wr = ageW2 + (l - 10) * 400; basep = sh + 600;  len = 400; bv = ageb2[l - 10]; }
        else             { wr = genW2 + (l - 14) * 400; basep = sh + 1000; len = 400; bv = genb2[l - 14]; }
        float s = 0.f;
        for (int i = lane; i < len; i += 32) s += basep[i] * wr[i];
        for (int o = 16; o > 0; o >>= 1) s += __shfl_xor_sync(0xffffffffu, s, o);
        if (lane == 0) slog[l] = fmaxf(s + bv, 0.f);
    }
    __syncthreads();
    if (t == 0) {
        float m = slog[0];
        for (int i = 1; i < 10; i++) m = fmaxf(m, slog[i]);
        float e[10], sum = 0.f;
        for (int i = 0; i < 10; i++) { e[i] = expf(slog[i] - m); sum += e[i]; }
        for (int i = 0; i < 10; i++) out[b * 10 + i] = e[i] / sum;
    } else if (t == 32) {
        float m = slog[10];
        for (int i = 11; i < 14; i++) m = fmaxf(m, slog[i]);
        float e[4], sum = 0.f;
        for (int i = 0; i < 4; i++) { e[i] = expf(slog[10 + i] - m); sum += e[i]; }
        for (int i = 0; i < 4; i++) out[640 + b * 4 + i] = e[i] / sum;
    } else if (t == 64) {
        float m = fmaxf(slog[14], slog[15]);
        float e0 = expf(slog[14] - m), e1 = expf(slog[15] - m);
        float inv = 1.f / (e0 + e1);
        out[896 + b * 2]     = e0 * inv;
        out[896 + b * 2 + 1] = e1 * inv;
    }
}

extern "C" void kernel_launch(void* const* d_in, const int* in_sizes, int n_in,
                              void* d_out, int out_size) {
    const float* x      = (const float*)d_in[0];
    const float* base_W = (const float*)d_in[1];
    const float* base_b = (const float*)d_in[2];
    const float* hW     = (const float*)d_in[3];
    const float* hb     = (const float*)d_in[4];
    const float* stW1   = (const float*)d_in[5];
    const float* stb1   = (const float*)d_in[6];
    const float* stW2   = (const float*)d_in[7];
    const float* stb2   = (const float*)d_in[8];
    const float* ageW1  = (const float*)d_in[9];
    const float* ageb1  = (const float*)d_in[10];
    const float* ageW2  = (const float*)d_in[11];
    const float* ageb2  = (const float*)d_in[12];
    const float* genW1  = (const float*)d_in[13];
    const float* genb1  = (const float*)d_in[14];
    const float* genW2  = (const float*)d_in[15];
    const float* genb2  = (const float*)d_in[16];
    float* out = (float*)d_out;

    float *pc = nullptr, *ph = nullptr;
    cudaGetSymbolAddress((void**)&pc, g_concat);
    cudaGetSymbolAddress((void**)&ph, g_h);

    cudaFuncSetAttribute(gemm1, cudaFuncAttributeMaxDynamicSharedMemorySize, G1_SMEM);

    init_all<<<(INIT_TOTAL + 255) / 256, 256>>>(base_b, hb, stb1, ageb1, genb1);
    hist_minmax<<<BB * CHN * 4, 256>>>(x);
    hist_bins<<<BB * CHN * 4, 256>>>(x);
    gemm1<<<dim3(2, KSPLIT), 384, G1_SMEM>>>(x, base_W);

    mid_gemm<<<dim3(7, 26), 256>>>(pc, CONC, CONC, hW, ph, HID, HID, 0);
    heads1_gemm<<<dim3(22, 13), 256>>>(stW1, ageW1, genW1);
    heads_kernel<<<BB, 256>>>(stW2, stb2, ageW2, ageb2, genW2, genb2, out);
}